// round 2
// baseline (speedup 1.0000x reference)
#include <cuda_runtime.h>

#define NT 256
#define STEPS 15
#define SPEED 5.0f
#define NCOLS_IN 18
#define NCOLS_OUT 178

__global__ void __launch_bounds__(NT, 2) prog_kernel(
    const float* __restrict__ x,
    const float* __restrict__ c1w, const float* __restrict__ c1b,
    const float* __restrict__ c2w, const float* __restrict__ c2b,
    const float* __restrict__ l1w, const float* __restrict__ l1b,
    const float* __restrict__ l2w, const float* __restrict__ l2b,
    float* __restrict__ out, int n)
{
    // Packed per-output-neuron weight block, stride 12 floats (48B, 16B-aligned):
    //  [0..3]  l1w[0..3][j]   (transposed)   -> LDS.128
    //  [4]     l1b[j], [5..7] l2w[j][0..2]   -> LDS.128
    //  [8..9]  l2w[j][3..4]                  -> LDS.64
    //  [10..11] pad
    __shared__ float s_w[32 * 12];
    __shared__ float s_cb[12];   // c1w0,c1w1,c1b, c2w0,c2w1,c2b, l2b[0..4]

    const int t = threadIdx.x;
    if (t < 32) {
        const int j = t;
        s_w[12 * j + 0] = l1w[0 * 32 + j];
        s_w[12 * j + 1] = l1w[1 * 32 + j];
        s_w[12 * j + 2] = l1w[2 * 32 + j];
        s_w[12 * j + 3] = l1w[3 * 32 + j];
        s_w[12 * j + 4] = l1b[j];
        s_w[12 * j + 5] = l2w[5 * j + 0];
        s_w[12 * j + 6] = l2w[5 * j + 1];
        s_w[12 * j + 7] = l2w[5 * j + 2];
        s_w[12 * j + 8] = l2w[5 * j + 3];
        s_w[12 * j + 9] = l2w[5 * j + 4];
        s_w[12 * j + 10] = 0.0f;
        s_w[12 * j + 11] = 0.0f;
    } else if (t < 64) {
        const int u = t - 32;
        if (u < 12) {
            float v;
            if      (u == 0) v = c1w[0];
            else if (u == 1) v = c1w[1];
            else if (u == 2) v = c1b[0];
            else if (u == 3) v = c2w[0];
            else if (u == 4) v = c2w[1];
            else if (u == 5) v = c2b[0];
            else if (u < 11) v = l2b[u - 6];
            else             v = 0.0f;
            s_cb[u] = v;
        }
    }
    __syncthreads();

    const int row = blockIdx.x * NT + t;
    if (row >= n) return;

    const float c1w0 = s_cb[0], c1w1 = s_cb[1], c1b0 = s_cb[2];
    const float c2w0 = s_cb[3], c2w1 = s_cb[4], c2b0 = s_cb[5];
    const float l2b0 = s_cb[6], l2b1 = s_cb[7], l2b2 = s_cb[8];
    const float l2b3 = s_cb[9], l2b4 = s_cb[10];

    // ---- load state row (18 floats, 8B-aligned) ----
    const float* xr = x + (long long)row * NCOLS_IN;
    float2 v0 = *(const float2*)(xr + 0);
    float2 v1 = *(const float2*)(xr + 2);
    float2 v2 = *(const float2*)(xr + 4);
    float2 v3 = *(const float2*)(xr + 6);
    float2 v4 = *(const float2*)(xr + 8);
    float2 v8 = *(const float2*)(xr + 16);
    float s0 = v0.x, s1 = v0.y, s2 = v1.x, s3 = v1.y;
    float s4 = v2.x, s5 = v2.y, s6 = v3.x, s7 = v3.y;
    float s8 = v4.x, s9 = v4.y, s10, s11, s12, s13, s14, s15, s16;
    float s17 = v8.y;

    // initial distance
    {
        float d13 = s1 - s3, d24 = s2 - s4;
        s10 = fmaf(d13, d13, d24 * d24);
    }

    float* orow = out + (long long)row * NCOLS_OUT;

    // traj0 = s[10,1,2,3,4,5,6,7,8,17] at columns [18,28)
    {
        float* o = orow + 18;
        *(float2*)(o + 0) = make_float2(s10, s1);
        *(float2*)(o + 2) = make_float2(s2, s3);
        *(float2*)(o + 4) = make_float2(s4, s5);
        *(float2*)(o + 6) = make_float2(s6, s7);
        *(float2*)(o + 8) = make_float2(s8, s17);
    }

    s11 = s12 = s13 = s14 = s15 = s16 = 0.0f;

    #pragma unroll 1
    for (int step = 0; step < STEPS; step++) {
        // feat = s[1,2,3,4,9,17]
        const float f0 = s1, f1 = s2, f2 = s3, f3 = s4, f4 = s9, f5 = s17;

        float h10 = fmaxf(fmaf(c1w1, f1, fmaf(c1w0, f0, c1b0)), 0.0f);
        float h11 = fmaxf(fmaf(c1w1, f2, fmaf(c1w0, f1, c1b0)), 0.0f);
        float h12 = fmaxf(fmaf(c1w1, f3, fmaf(c1w0, f2, c1b0)), 0.0f);
        float h13 = fmaxf(fmaf(c1w1, f4, fmaf(c1w0, f3, c1b0)), 0.0f);
        float h14 = fmaxf(fmaf(c1w1, f5, fmaf(c1w0, f4, c1b0)), 0.0f);

        float h20 = fmaxf(fmaf(c2w1, h11, fmaf(c2w0, h10, c2b0)), 0.0f);
        float h21 = fmaxf(fmaf(c2w1, h12, fmaf(c2w0, h11, c2b0)), 0.0f);
        float h22 = fmaxf(fmaf(c2w1, h13, fmaf(c2w0, h12, c2b0)), 0.0f);
        float h23 = fmaxf(fmaf(c2w1, h14, fmaf(c2w0, h13, c2b0)), 0.0f);

        float p0 = l2b0, p1 = l2b1, p2 = l2b2, p3 = l2b3, p4 = l2b4;

        #pragma unroll
        for (int j = 0; j < 32; j++) {
            const float4 wa = *(const float4*)(s_w + 12 * j + 0);
            const float4 wb = *(const float4*)(s_w + 12 * j + 4);
            const float2 wc = *(const float2*)(s_w + 12 * j + 8);
            float h3 = fmaf(h23, wa.w, fmaf(h22, wa.z, fmaf(h21, wa.y, fmaf(h20, wa.x, wb.x))));
            h3 = fmaxf(h3, 0.0f);
            p0 = fmaf(h3, wb.y, p0);
            p1 = fmaf(h3, wb.z, p1);
            p2 = fmaf(h3, wb.w, p2);
            p3 = fmaf(h3, wc.x, p3);
            p4 = fmaf(h3, wc.y, p4);
        }

        // sigmoid, full precision
        p0 = 1.0f / (1.0f + expf(-p0));
        p1 = 1.0f / (1.0f + expf(-p1));
        p2 = 1.0f / (1.0f + expf(-p2));
        p3 = 1.0f / (1.0f + expf(-p3));
        p4 = 1.0f / (1.0f + expf(-p4));

        s5 = p0; s6 = p1; s7 = p2; s8 = p3; s17 = p4;

        const float a = p1 - p0, b = p2 - p0, c = p3 - p0;
        const float d = p2 - p1, e = p3 - p1, f = p3 - p2;
        s11 = a; s12 = b; s13 = c; s14 = d; s15 = e; s16 = f;

        const float dx_c = (c <= 0.0f) ? 0.0f : SPEED;
        const float st_c = (c <= 0.0f) ? 0.0f : 3.0f;
        const float dx_f = (f <= 0.0f) ? 0.0f : SPEED;
        const float st_f = (f <= 0.0f) ? 2.0f : 3.0f;
        const float dx_e = (e <= 0.0f) ? -SPEED : SPEED;
        const float st_e = (e <= 0.0f) ? 1.0f : 3.0f;
        const float dx_b = (b <= 0.0f) ? dx_c : dx_f;
        const float st_b = (b <= 0.0f) ? st_c : st_f;
        const float dx_d = (d <= 0.0f) ? dx_e : dx_f;
        const float st_d = (d <= 0.0f) ? st_e : st_f;
        const float dx   = (a <= 0.0f) ? dx_b : dx_d;
        const float st   = (a <= 0.0f) ? st_b : st_d;

        s1 += dx;
        s9 = st;
        s2 += SPEED;
        s3 += SPEED;
        s0 += 1.0f;
        {
            float d13 = s1 - s3, d24 = s2 - s4;
            s10 = fmaf(d13, d13, d24 * d24);
        }

        // record traj: columns [18 + 10*(step+1), +10)
        float* o = orow + 18 + 10 * (step + 1);
        *(float2*)(o + 0) = make_float2(s10, s1);
        *(float2*)(o + 2) = make_float2(s2, s3);
        *(float2*)(o + 4) = make_float2(s4, s5);
        *(float2*)(o + 6) = make_float2(s6, s7);
        *(float2*)(o + 8) = make_float2(s8, s17);
    }

    // final state -> columns [0,18)
    *(float2*)(orow + 0)  = make_float2(s0, s1);
    *(float2*)(orow + 2)  = make_float2(s2, s3);
    *(float2*)(orow + 4)  = make_float2(s4, s5);
    *(float2*)(orow + 6)  = make_float2(s6, s7);
    *(float2*)(orow + 8)  = make_float2(s8, s9);
    *(float2*)(orow + 10) = make_float2(s10, s11);
    *(float2*)(orow + 12) = make_float2(s12, s13);
    *(float2*)(orow + 14) = make_float2(s14, s15);
    *(float2*)(orow + 16) = make_float2(s16, s17);
}

extern "C" void kernel_launch(void* const* d_in, const int* in_sizes, int n_in,
                              void* d_out, int out_size)
{
    const float* x   = (const float*)d_in[0];
    const float* c1w = (const float*)d_in[1];
    const float* c1b = (const float*)d_in[2];
    const float* c2w = (const float*)d_in[3];
    const float* c2b = (const float*)d_in[4];
    const float* l1w = (const float*)d_in[5];
    const float* l1b = (const float*)d_in[6];
    const float* l2w = (const float*)d_in[7];
    const float* l2b = (const float*)d_in[8];
    float* out = (float*)d_out;

    const int n = in_sizes[0] / NCOLS_IN;
    const int blocks = (n + NT - 1) / NT;
    prog_kernel<<<blocks, NT>>>(x, c1w, c1b, c2w, c2b, l1w, l1b, l2w, l2b, out, n);
}